// round 6
// baseline (speedup 1.0000x reference)
#include <cuda_runtime.h>

#define N_TOTAL   100000
#define FEAT      128
#define NB_ROWS   50000
#define KNEI      16
#define EMB       128
#define RTILE     64
#define TPB       256
#define NBLK      ((NB_ROWS + RTILE - 1) / RTILE)   // 782
#define GRID      296                                // 2 CTAs x 148 SMs (<=152)
#define AGG_LD    132
#define SMEM_BYTES ((FEAT * EMB + RTILE * AGG_LD) * 4)   // 99328

typedef unsigned long long ull;

// Scratch (allocation-free rule: __device__ globals)
__device__ float g_psum[GRID * EMB];
__device__ float g_psq [GRID * EMB];
__device__ float g_scale[EMB];
__device__ float g_bias [EMB];
__device__ unsigned int g_arrival = 0;
__device__ unsigned int g_done    = 0;
__device__ unsigned int g_ready   = 0;

// ---- packed f32x2 helpers (Blackwell) ----
__device__ __forceinline__ ull pack2(float x) {
    ull r;
    asm("mov.b64 %0, {%1, %1};" : "=l"(r) : "r"(__float_as_uint(x)));
    return r;
}
__device__ __forceinline__ void fma2(ull& d, ull a, ull b) {
    asm("fma.rn.f32x2 %0, %1, %2, %0;" : "+l"(d) : "l"(a), "l"(b));
}
__device__ __forceinline__ void unpack2(ull v, float& lo, float& hi) {
    unsigned int l, h;
    asm("mov.b64 {%0, %1}, %2;" : "=r"(l), "=r"(h) : "l"(v));
    lo = __uint_as_float(l);
    hi = __uint_as_float(h);
}

// ============================================================================
// Persistent kernel: gather-mean + GEMM over ~2.6 tiles/CTA, in-register
// cross-tile stats, grid barrier, last-CTA finalize, per-CTA BN apply.
// ============================================================================
__global__ void __launch_bounds__(TPB, 2)
fused_persist(const float* __restrict__ raw,
              const float* __restrict__ W,
              const int* __restrict__ nidx,
              const float* __restrict__ gamma,
              const float* __restrict__ beta,
              float* __restrict__ out)
{
    extern __shared__ float smem[];
    float* s_w   = smem;              // [128][128] weight, row k contiguous
    float* s_agg = smem + FEAT * EMB; // [64][AGG_LD]

    const int tid  = threadIdx.x;
    const int bid  = blockIdx.x;
    const int warp = tid >> 5, lane = tid & 31;
    const int tx = tid & 15, ty = tid >> 4;

    // --- load weight to smem once per CTA ---
    {
        const float4* Wv = (const float4*)W;
        float4* sv = (float4*)s_w;
        for (int i = tid; i < FEAT * EMB / 4; i += TPB) sv[i] = Wv[i];
    }

    // Cross-tile per-thread column accumulators (8 columns each).
    float cs[8], cq[8];
    #pragma unroll
    for (int k = 0; k < 8; k++) { cs[k] = 0.f; cq[k] = 0.f; }

    // =========================== compute phase ===========================
    for (int t = bid; t < NBLK; t += GRID) {
        const int rowBase = t * RTILE;
        __syncthreads();   // s_agg safe to overwrite (covers W-load on iter 0)

        // --- gather + mean: 8 warps x 8 rows; lane covers float4 cols ---
        #pragma unroll
        for (int i = 0; i < 8; i++) {
            const int rl = warp * 8 + i;
            const int rg = rowBase + rl;
            float4 a4 = make_float4(0.f, 0.f, 0.f, 0.f);
            if (rg < NB_ROWS) {
                int my = 0;
                if (lane < KNEI) my = nidx[rg * KNEI + lane];
                #pragma unroll
                for (int k = 0; k < KNEI; k++) {
                    const int id = __shfl_sync(0xffffffffu, my, k);
                    const float4 v =
                        ((const float4*)(raw + (long long)id * FEAT))[lane];
                    a4.x += v.x; a4.y += v.y; a4.z += v.z; a4.w += v.w;
                }
                const float inv = 1.0f / KNEI;
                a4.x *= inv; a4.y *= inv; a4.z *= inv; a4.w *= inv;
            }
            ((float4*)(s_agg + rl * AGG_LD))[lane] = a4;
        }
        __syncthreads();

        // --- GEMM: thread (ty,tx): rows ty*4..+3, cols tx*4..+3 & 64+tx*4..+3
        ull acc[4][4];
        #pragma unroll
        for (int i = 0; i < 4; i++)
            #pragma unroll
            for (int j = 0; j < 4; j++) acc[i][j] = 0ULL;

        const float* aBase = s_agg + (ty * 4) * AGG_LD;
        const float* bBase = s_w + tx * 4;

        #pragma unroll 2
        for (int k0 = 0; k0 < FEAT; k0 += 4) {
            float4 a[4];
            #pragma unroll
            for (int i = 0; i < 4; i++)
                a[i] = *(const float4*)(aBase + i * AGG_LD + k0);

            #pragma unroll
            for (int kk = 0; kk < 4; kk++) {
                const ulonglong2 b0 =
                    *(const ulonglong2*)(bBase + (k0 + kk) * EMB);
                const ulonglong2 b1 =
                    *(const ulonglong2*)(bBase + (k0 + kk) * EMB + 64);
                #pragma unroll
                for (int i = 0; i < 4; i++) {
                    const float as = (kk == 0) ? a[i].x : (kk == 1) ? a[i].y
                                   : (kk == 2) ? a[i].z : a[i].w;
                    const ull av = pack2(as);
                    fma2(acc[i][0], av, b0.x);
                    fma2(acc[i][1], av, b0.y);
                    fma2(acc[i][2], av, b1.x);
                    fma2(acc[i][3], av, b1.y);
                }
            }
        }

        // --- write pre-BN x + accumulate column stats in registers ---
        #pragma unroll
        for (int i = 0; i < 4; i++) {
            const int rg = rowBase + ty * 4 + i;
            if (rg < NB_ROWS) {
                ulonglong2 v0; v0.x = acc[i][0]; v0.y = acc[i][1];
                ulonglong2 v1; v1.x = acc[i][2]; v1.y = acc[i][3];
                *(ulonglong2*)(out + (long long)rg * EMB + tx * 4)      = v0;
                *(ulonglong2*)(out + (long long)rg * EMB + 64 + tx * 4) = v1;
            }
            // invalid rows hold exact 0 accumulators -> contribute nothing
            #pragma unroll
            for (int j = 0; j < 4; j++) {
                float x0, x1;
                unpack2(acc[i][j], x0, x1);
                cs[2 * j]     += x0;  cq[2 * j]     += x0 * x0;
                cs[2 * j + 1] += x1;  cq[2 * j + 1] += x1 * x1;
            }
        }
    }

    // ====================== block-level stats reduce ======================
    __syncthreads();   // all GEMM reads of s_agg finished
    float* s_sum = s_agg;          // [16][128]
    float* s_sq  = s_agg + 2048;   // [16][128]
    #pragma unroll
    for (int k = 0; k < 8; k++) {
        const int j = k >> 1;
        const int c = ((j < 2) ? (tx * 4 + 2 * j)
                               : (64 + tx * 4 + 2 * (j - 2))) + (k & 1);
        s_sum[ty * 128 + c] = cs[k];
        s_sq [ty * 128 + c] = cq[k];
    }
    __syncthreads();
    if (tid < 128) {
        float s = 0.f, q = 0.f;
        #pragma unroll
        for (int t8 = 0; t8 < 16; t8++) {
            s += s_sum[t8 * 128 + tid];
            q += s_sq [t8 * 128 + tid];
        }
        g_psum[bid * 128 + tid] = s;
        g_psq [bid * 128 + tid] = q;
    }

    // ========================== grid barrier ==========================
    __threadfence();
    __shared__ unsigned int s_last;
    if (tid == 0)
        s_last = (atomicAdd(&g_arrival, 1u) == (unsigned)(GRID - 1)) ? 1u : 0u;
    __syncthreads();

    if (s_last) {
        // last CTA: reduce GRID partials (fixed order -> deterministic)
        const int c = tid & 127, p = tid >> 7;     // 2-way split
        float s = 0.f, q = 0.f;
        for (int b = p; b < GRID; b += 2) {
            s += g_psum[b * 128 + c];
            q += g_psq [b * 128 + c];
        }
        s_sum[p * 128 + c] = s;
        s_sq [p * 128 + c] = q;
        __syncthreads();
        if (tid < 128) {
            const float ss = s_sum[tid] + s_sum[128 + tid];
            const float qq = s_sq [tid] + s_sq [128 + tid];
            const float invN = 1.0f / (float)NB_ROWS;
            const float mean = ss * invN;
            const float var  = qq * invN - mean * mean;
            const float sc   = gamma[tid] * rsqrtf(var + 1e-5f);
            g_scale[tid] = sc;
            g_bias [tid] = beta[tid] - mean * sc;
        }
        __syncthreads();
        __threadfence();
        if (tid == 0) atomicExch(&g_ready, 1u);
    } else {
        if (tid == 0) {
            unsigned int r;
            do {
                asm volatile("ld.acquire.gpu.b32 %0, [%1];"
                             : "=r"(r) : "l"(&g_ready));
                if (!r) __nanosleep(64);
            } while (!r);
        }
        __syncthreads();
    }

    // ================== BN apply + LeakyReLU on own tiles ==================
    if (tid < 128) {
        s_w[tid]       = g_scale[tid];
        s_w[128 + tid] = g_bias[tid];
    }
    __syncthreads();

    for (int t = bid; t < NBLK; t += GRID) {
        const int rowBase = t * RTILE;
        float4* o4 = (float4*)(out + (long long)rowBase * EMB);
        #pragma unroll
        for (int j = 0; j < 8; j++) {
            const int i = tid + j * TPB;           // 0..2047 float4s
            const int row = i >> 5;
            if (rowBase + row < NB_ROWS) {
                const int c4 = i & 31;
                float4 v = o4[i];
                const float4 sc = ((const float4*)s_w)[c4];
                const float4 bs = ((const float4*)(s_w + 128))[c4];
                float x;
                x = v.x * sc.x + bs.x; v.x = (x >= 0.f) ? x : 0.01f * x;
                x = v.y * sc.y + bs.y; v.y = (x >= 0.f) ? x : 0.01f * x;
                x = v.z * sc.z + bs.z; v.z = (x >= 0.f) ? x : 0.01f * x;
                x = v.w * sc.w + bs.w; v.w = (x >= 0.f) ? x : 0.01f * x;
                o4[i] = v;
            }
        }
    }

    // ---- exit barrier: last CTA to finish resets counters for replay ----
    __threadfence();
    __syncthreads();
    if (tid == 0) {
        if (atomicAdd(&g_done, 1u) == (unsigned)(GRID - 1)) {
            g_arrival = 0;
            g_done    = 0;
            g_ready   = 0;
            __threadfence();
        }
    }
}

// ============================================================================
extern "C" void kernel_launch(void* const* d_in, const int* in_sizes, int n_in,
                              void* d_out, int out_size)
{
    const float* raw   = (const float*)d_in[0];
    const float* W     = (const float*)d_in[1];
    const float* gamma = (const float*)d_in[2];
    const float* beta  = (const float*)d_in[3];
    const int*   nidx  = (const int*)d_in[4];
    float* out = (float*)d_out;

    cudaFuncSetAttribute(fused_persist,
                         cudaFuncAttributeMaxDynamicSharedMemorySize,
                         SMEM_BYTES);

    fused_persist<<<GRID, TPB, SMEM_BYTES>>>(raw, W, nidx, gamma, beta, out);
}

// round 7
// speedup vs baseline: 1.0152x; 1.0152x over previous
#include <cuda_runtime.h>

#define N_TOTAL   100000
#define FEAT      128
#define NB_ROWS   50000
#define KNEI      16
#define EMB       128
#define RTILE     64
#define TPB       256
#define NBLK      ((NB_ROWS + RTILE - 1) / RTILE)   // 782
#define GRID      391                                // exactly 2 tiles/CTA
#define AGG_LD    132
#define KCHUNK    32
#define NCHUNK    (FEAT / KCHUNK)                    // 4
#define SMEM_FLOATS (RTILE * AGG_LD + 2 * KCHUNK * EMB)   // 8448 + 8192
#define SMEM_BYTES  (SMEM_FLOATS * 4)                // 66560 -> 3 CTAs/SM

typedef unsigned long long ull;

// Scratch (allocation-free rule: __device__ globals)
__device__ float g_psum[GRID * EMB];
__device__ float g_psq [GRID * EMB];
__device__ float g_scale[EMB];
__device__ float g_bias [EMB];
__device__ unsigned int g_arrival = 0;
__device__ unsigned int g_done    = 0;
__device__ unsigned int g_ready   = 0;

// ---- packed f32x2 helpers (Blackwell) ----
__device__ __forceinline__ ull pack2(float x) {
    ull r;
    asm("mov.b64 %0, {%1, %1};" : "=l"(r) : "r"(__float_as_uint(x)));
    return r;
}
__device__ __forceinline__ void fma2(ull& d, ull a, ull b) {
    asm("fma.rn.f32x2 %0, %1, %2, %0;" : "+l"(d) : "l"(a), "l"(b));
}
__device__ __forceinline__ void add2(ull& d, ull a) {
    asm("add.rn.f32x2 %0, %0, %1;" : "+l"(d) : "l"(a));
}
__device__ __forceinline__ void unpack2(ull v, float& lo, float& hi) {
    unsigned int l, h;
    asm("mov.b64 {%0, %1}, %2;" : "=r"(l), "=r"(h) : "l"(v));
    lo = __uint_as_float(l);
    hi = __uint_as_float(h);
}
// ---- cp.async 16B ----
__device__ __forceinline__ void cp16(unsigned int daddr, const void* gptr) {
    asm volatile("cp.async.cg.shared.global [%0], [%1], 16;"
                 :: "r"(daddr), "l"(gptr));
}
__device__ __forceinline__ void cp_commit() {
    asm volatile("cp.async.commit_group;");
}
__device__ __forceinline__ void cp_wait_all() {
    asm volatile("cp.async.wait_group 0;" ::: "memory");
}

// ============================================================================
// Persistent kernel, 3 CTAs/SM: gather-mean + GEMM with cp.async-streamed W
// k-chunks (double buffered), in-register packed stats, grid barrier,
// last-CTA finalize, per-CTA BN apply.  Exactly 2 tiles per CTA.
// ============================================================================
__global__ void __launch_bounds__(TPB, 3)
fused_persist(const float* __restrict__ raw,
              const float* __restrict__ W,
              const int* __restrict__ nidx,
              const float* __restrict__ gamma,
              const float* __restrict__ beta,
              float* __restrict__ out)
{
    extern __shared__ float smem[];
    float* s_agg = smem;                    // [64][AGG_LD]
    float* s_b   = smem + RTILE * AGG_LD;   // [2][KCHUNK][128]

    const int tid  = threadIdx.x;
    const int bid  = blockIdx.x;
    const int warp = tid >> 5, lane = tid & 31;
    const int tx = tid & 15, ty = tid >> 4;

    const unsigned int sb_base =
        (unsigned int)__cvta_generic_to_shared(s_b) + tid * 16;

    // Cross-tile packed column stats: cs[j]/cq[j] are (col pair) f32x2.
    ull cs[4], cq[4];
    #pragma unroll
    for (int j = 0; j < 4; j++) { cs[j] = 0ULL; cq[j] = 0ULL; }

    // =========================== compute phase ===========================
    for (int t = bid; t < NBLK; t += GRID) {
        const int rowBase = t * RTILE;
        __syncthreads();   // prior tile's reads of s_agg / s_b complete

        // prefetch W chunk 0 into s_b buf 0 (16KB, 4 x cp16 per thread)
        {
            const float4* src = (const float4*)W + tid;
            #pragma unroll
            for (int j = 0; j < 4; j++)
                cp16(sb_base + j * 4096, src + j * 256);
            cp_commit();
        }

        // --- gather + mean: 8 warps x 8 rows; lane covers float4 cols ---
        #pragma unroll
        for (int i = 0; i < 8; i++) {
            const int rl = warp * 8 + i;
            const int rg = rowBase + rl;
            float4 a4 = make_float4(0.f, 0.f, 0.f, 0.f);
            if (rg < NB_ROWS) {
                int my = 0;
                if (lane < KNEI) my = nidx[rg * KNEI + lane];
                #pragma unroll
                for (int k = 0; k < KNEI; k++) {
                    const int id = __shfl_sync(0xffffffffu, my, k);
                    const float4 v =
                        ((const float4*)(raw + (long long)id * FEAT))[lane];
                    a4.x += v.x; a4.y += v.y; a4.z += v.z; a4.w += v.w;
                }
                const float inv = 1.0f / KNEI;
                a4.x *= inv; a4.y *= inv; a4.z *= inv; a4.w *= inv;
            }
            ((float4*)(s_agg + rl * AGG_LD))[lane] = a4;
        }
        cp_wait_all();
        __syncthreads();   // s_agg stores + chunk0 visible

        // --- GEMM: thread (ty,tx): rows ty*4..+3, cols tx*4..+3 & 64+tx*4..+3
        ull acc[4][4];
        #pragma unroll
        for (int i = 0; i < 4; i++)
            #pragma unroll
            for (int j = 0; j < 4; j++) acc[i][j] = 0ULL;

        #pragma unroll
        for (int c = 0; c < NCHUNK; c++) {
            if (c < NCHUNK - 1) {
                const float4* src =
                    (const float4*)(W + (c + 1) * KCHUNK * EMB) + tid;
                const unsigned int dst =
                    sb_base + ((c + 1) & 1) * (KCHUNK * EMB * 4);
                #pragma unroll
                for (int j = 0; j < 4; j++)
                    cp16(dst + j * 4096, src + j * 256);
                cp_commit();
            }

            const float* bBase = s_b + (c & 1) * (KCHUNK * EMB) + tx * 4;
            const float* aBase = s_agg + (ty * 4) * AGG_LD + c * KCHUNK;

            #pragma unroll 2
            for (int kc = 0; kc < KCHUNK; kc += 4) {
                float4 a[4];
                #pragma unroll
                for (int i = 0; i < 4; i++)
                    a[i] = *(const float4*)(aBase + i * AGG_LD + kc);

                #pragma unroll
                for (int kk = 0; kk < 4; kk++) {
                    const ulonglong2 b0 =
                        *(const ulonglong2*)(bBase + (kc + kk) * EMB);
                    const ulonglong2 b1 =
                        *(const ulonglong2*)(bBase + (kc + kk) * EMB + 64);
                    #pragma unroll
                    for (int i = 0; i < 4; i++) {
                        const float as = (kk == 0) ? a[i].x : (kk == 1) ? a[i].y
                                       : (kk == 2) ? a[i].z : a[i].w;
                        const ull av = pack2(as);
                        fma2(acc[i][0], av, b0.x);
                        fma2(acc[i][1], av, b0.y);
                        fma2(acc[i][2], av, b1.x);
                        fma2(acc[i][3], av, b1.y);
                    }
                }
            }

            if (c < NCHUNK - 1) {
                cp_wait_all();
                __syncthreads();
            }
        }

        // --- write pre-BN x + accumulate packed column stats ---
        #pragma unroll
        for (int i = 0; i < 4; i++) {
            const int rg = rowBase + ty * 4 + i;
            if (rg < NB_ROWS) {
                ulonglong2 v0; v0.x = acc[i][0]; v0.y = acc[i][1];
                ulonglong2 v1; v1.x = acc[i][2]; v1.y = acc[i][3];
                *(ulonglong2*)(out + (long long)rg * EMB + tx * 4)      = v0;
                *(ulonglong2*)(out + (long long)rg * EMB + 64 + tx * 4) = v1;
            }
            // invalid rows hold exact-0 accumulators -> contribute nothing
            #pragma unroll
            for (int j = 0; j < 4; j++) {
                add2(cs[j], acc[i][j]);
                fma2(cq[j], acc[i][j], acc[i][j]);
            }
        }
    }

    // ====================== block-level stats reduce ======================
    __syncthreads();   // all GEMM reads of s_agg finished
    float* s_sum = s_agg;          // [16][128]
    float* s_sq  = s_agg + 2048;   // [16][128]
    #pragma unroll
    for (int j = 0; j < 4; j++) {
        float s0, s1, q0, q1;
        unpack2(cs[j], s0, s1);
        unpack2(cq[j], q0, q1);
        const int c = (j < 2) ? (tx * 4 + 2 * j) : (64 + tx * 4 + 2 * (j - 2));
        s_sum[ty * 128 + c]     = s0;
        s_sum[ty * 128 + c + 1] = s1;
        s_sq [ty * 128 + c]     = q0;
        s_sq [ty * 128 + c + 1] = q1;
    }
    __syncthreads();
    if (tid < 128) {
        float s = 0.f, q = 0.f;
        #pragma unroll
        for (int t8 = 0; t8 < 16; t8++) {
            s += s_sum[t8 * 128 + tid];
            q += s_sq [t8 * 128 + tid];
        }
        g_psum[bid * 128 + tid] = s;
        g_psq [bid * 128 + tid] = q;
    }

    // ========================== grid barrier ==========================
    __threadfence();
    __shared__ unsigned int s_last;
    if (tid == 0)
        s_last = (atomicAdd(&g_arrival, 1u) == (unsigned)(GRID - 1)) ? 1u : 0u;
    __syncthreads();

    if (s_last) {
        const int c = tid & 127, p = tid >> 7;     // 2-way split
        float s = 0.f, q = 0.f;
        for (int b = p; b < GRID; b += 2) {
            s += g_psum[b * 128 + c];
            q += g_psq [b * 128 + c];
        }
        s_sum[p * 128 + c] = s;
        s_sq [p * 128 + c] = q;
        __syncthreads();
        if (tid < 128) {
            const float ss = s_sum[tid] + s_sum[128 + tid];
            const float qq = s_sq [tid] + s_sq [128 + tid];
            const float invN = 1.0f / (float)NB_ROWS;
            const float mean = ss * invN;
            const float var  = qq * invN - mean * mean;
            const float sc   = gamma[tid] * rsqrtf(var + 1e-5f);
            g_scale[tid] = sc;
            g_bias [tid] = beta[tid] - mean * sc;
        }
        __syncthreads();
        __threadfence();
        if (tid == 0) atomicExch(&g_ready, 1u);
    } else {
        if (tid == 0) {
            unsigned int r;
            do {
                asm volatile("ld.acquire.gpu.b32 %0, [%1];"
                             : "=r"(r) : "l"(&g_ready));
                if (!r) __nanosleep(64);
            } while (!r);
        }
        __syncthreads();
    }

    // ================== BN apply + LeakyReLU on own tiles ==================
    __syncthreads();
    if (tid < 128) {
        s_agg[tid]       = g_scale[tid];
        s_agg[128 + tid] = g_bias[tid];
    }
    __syncthreads();

    for (int t = bid; t < NBLK; t += GRID) {
        const int rowBase = t * RTILE;
        float4* o4 = (float4*)(out + (long long)rowBase * EMB);
        #pragma unroll
        for (int j = 0; j < 8; j++) {
            const int i = tid + j * TPB;           // 0..2047 float4s
            const int row = i >> 5;
            if (rowBase + row < NB_ROWS) {
                const int c4 = i & 31;
                float4 v = o4[i];
                const float4 sc = ((const float4*)s_agg)[c4];
                const float4 bs = ((const float4*)(s_agg + 128))[c4];
                float x;
                x = v.x * sc.x + bs.x; v.x = (x >= 0.f) ? x : 0.01f * x;
                x = v.y * sc.y + bs.y; v.y = (x >= 0.f) ? x : 0.01f * x;
                x = v.z * sc.z + bs.z; v.z = (x >= 0.f) ? x : 0.01f * x;
                x = v.w * sc.w + bs.w; v.w = (x >= 0.f) ? x : 0.01f * x;
                o4[i] = v;
            }
        }
    }

    // ---- exit: last CTA to finish resets counters for graph replay ----
    __threadfence();
    __syncthreads();
    if (tid == 0) {
        if (atomicAdd(&g_done, 1u) == (unsigned)(GRID - 1)) {
            g_arrival = 0;
            g_done    = 0;
            g_ready   = 0;
            __threadfence();
        }
    }
}

// ============================================================================
extern "C" void kernel_launch(void* const* d_in, const int* in_sizes, int n_in,
                              void* d_out, int out_size)
{
    const float* raw   = (const float*)d_in[0];
    const float* W     = (const float*)d_in[1];
    const float* gamma = (const float*)d_in[2];
    const float* beta  = (const float*)d_in[3];
    const int*   nidx  = (const int*)d_in[4];
    float* out = (float*)d_out;

    cudaFuncSetAttribute(fused_persist,
                         cudaFuncAttributeMaxDynamicSharedMemorySize,
                         SMEM_BYTES);

    fused_persist<<<GRID, TPB, SMEM_BYTES>>>(raw, W, nidx, gamma, beta, out);
}

// round 9
// speedup vs baseline: 1.1099x; 1.0932x over previous
#include <cuda_runtime.h>
#include <cstdint>

#define FEAT     128
#define NB_ROWS  50000
#define KNEI     16
#define EMB      128
#define MTILE    128
#define TPB      512
#define NTILE    ((NB_ROWS + MTILE - 1) / MTILE)   // 391
#define GRID     148                                // 1 CTA/SM, co-resident

// smem byte offsets
#define SM_W     0                   // [128][128] f32 weight (64KB)
#define SM_A     65536               // A[2][128][128] f32 (128KB)
#define SM_MISC  196608              // s_next etc.
#define SMEM_BYTES 196672

typedef unsigned long long ull;

// Scratch (allocation-free rule)
__device__ float g_psum[GRID * EMB];
__device__ float g_psq [GRID * EMB];
__device__ float g_scale[EMB];
__device__ float g_bias [EMB];
__device__ unsigned int g_tile    = 0;
__device__ unsigned int g_arrival = 0;
__device__ unsigned int g_done    = 0;
__device__ unsigned int g_ready   = 0;

// ---- packed f32x2 helpers (Blackwell) ----
__device__ __forceinline__ ull pack2(float x) {
    ull r;
    asm("mov.b64 %0, {%1, %1};" : "=l"(r) : "r"(__float_as_uint(x)));
    return r;
}
__device__ __forceinline__ void fma2(ull& d, ull a, ull b) {
    asm("fma.rn.f32x2 %0, %1, %2, %0;" : "+l"(d) : "l"(a), "l"(b));
}
__device__ __forceinline__ void add2(ull& d, ull a) {
    asm("add.rn.f32x2 %0, %0, %1;" : "+l"(d) : "l"(a));
}
__device__ __forceinline__ void unpack2(ull v, float& lo, float& hi) {
    unsigned int l, h;
    asm("mov.b64 {%0, %1}, %2;" : "=r"(l), "=r"(h) : "l"(v));
    lo = __uint_as_float(l);
    hi = __uint_as_float(h);
}

// ============================================================================
// Persistent kernel, 1 CTA/SM x 512 threads, dynamic tile scheduler,
// double-buffered A with gather-of-next-tile interleaved into the GEMM k-loop.
// ============================================================================
__global__ void __launch_bounds__(TPB, 1)
fused_pipe(const float* __restrict__ raw,
           const float* __restrict__ W,
           const int* __restrict__ nidx,
           const float* __restrict__ gamma,
           const float* __restrict__ beta,
           float* __restrict__ out)
{
    extern __shared__ char smem[];
    float* s_w = (float*)(smem + SM_W);
    unsigned int* s_next = (unsigned int*)(smem + SM_MISC);

    const int tid  = threadIdx.x;
    const int bid  = blockIdx.x;
    const int warp = tid >> 5, lane = tid & 31;
    const int tx = tid & 15, ty = tid >> 4;          // ty 0..31

    // --- load W resident (16384 floats) ---
    {
        const float4* Wv = (const float4*)W;
        float4* sv = (float4*)s_w;
        #pragma unroll
        for (int j = 0; j < 8; j++) sv[tid + j * TPB] = Wv[tid + j * TPB];
    }

    // --- fetch first tile ---
    if (tid == 0) s_next[0] = atomicAdd(&g_tile, 1u);
    __syncthreads();
    int t = (int)s_next[0];

    // --- preamble: gather full tile t into A[0] (8 rows per warp) ---
    {
        float* sA = (float*)(smem + SM_A);
        const int tBase = t * MTILE;
        #pragma unroll
        for (int i = 0; i < 8; i++) {
            const int rl = warp * 8 + i;
            const int rg = tBase + rl;
            float4 a4 = make_float4(0.f, 0.f, 0.f, 0.f);
            if (rg < NB_ROWS) {
                int my = 0;
                if (lane < KNEI) my = nidx[rg * KNEI + lane];
                #pragma unroll
                for (int k = 0; k < KNEI; k++) {
                    const int id = __shfl_sync(0xffffffffu, my, k);
                    const float4 v =
                        ((const float4*)(raw + (long long)id * FEAT))[lane];
                    a4.x += v.x; a4.y += v.y; a4.z += v.z; a4.w += v.w;
                }
                const float inv = 1.0f / KNEI;
                a4.x *= inv; a4.y *= inv; a4.z *= inv; a4.w *= inv;
            }
            ((float4*)(sA + rl * FEAT))[lane] = a4;
        }
    }

    // cross-tile packed column stats (col pairs per R-mapping)
    ull cs[4], cq[4];
    #pragma unroll
    for (int j = 0; j < 4; j++) { cs[j] = 0ULL; cq[j] = 0ULL; }

    int p = 0;

    // =========================== tile loop ===========================
    while (t < NTILE) {
        if (tid == 0) s_next[0] = atomicAdd(&g_tile, 1u);
        __syncthreads();       // A[p] complete; prior GEMM reads of A[p^1] done
        const int tn = (int)s_next[0];
        const int rowBase = t * MTILE;
        const int tnBase  = tn * MTILE;
        const bool haveNext = (tn < NTILE);

        float* sA  = (float*)(smem + SM_A) + p * (MTILE * FEAT);
        float* sAn = (float*)(smem + SM_A) + (p ^ 1) * (MTILE * FEAT);

        ull acc[4][4];
        #pragma unroll
        for (int i = 0; i < 4; i++)
            #pragma unroll
            for (int j = 0; j < 4; j++) acc[i][j] = 0ULL;

        const float* aBase = sA + (ty * 4) * FEAT;
        const float* bBase = s_w + tx * 4;

        #pragma unroll
        for (int c = 0; c < 4; c++) {
            // ---- gather 2 rows of next tile (rows warp*8+2c, +1) ----
            if (haveNext) {
                const int rl0 = warp * 8 + 2 * c;
                // lanes 0-15 carry row0's 16 neighbor ids, lanes 16-31 row1's
                const int rown = lane >> 4;
                const int rgL  = tnBase + rl0 + rown;
                int my = 0;
                if (rgL < NB_ROWS) my = nidx[rgL * KNEI + (lane & 15)];

                float4 a0 = make_float4(0.f, 0.f, 0.f, 0.f);
                float4 a1 = make_float4(0.f, 0.f, 0.f, 0.f);
                if (tnBase + rl0 < NB_ROWS) {
                    #pragma unroll
                    for (int k = 0; k < KNEI; k++) {
                        const int id = __shfl_sync(0xffffffffu, my, k);
                        const float4 v =
                            ((const float4*)(raw + (long long)id * FEAT))[lane];
                        a0.x += v.x; a0.y += v.y; a0.z += v.z; a0.w += v.w;
                    }
                }
                if (tnBase + rl0 + 1 < NB_ROWS) {
                    #pragma unroll
                    for (int k = 0; k < KNEI; k++) {
                        const int id = __shfl_sync(0xffffffffu, my, KNEI + k);
                        const float4 v =
                            ((const float4*)(raw + (long long)id * FEAT))[lane];
                        a1.x += v.x; a1.y += v.y; a1.z += v.z; a1.w += v.w;
                    }
                }
                const float inv = 1.0f / KNEI;
                a0.x *= inv; a0.y *= inv; a0.z *= inv; a0.w *= inv;
                a1.x *= inv; a1.y *= inv; a1.z *= inv; a1.w *= inv;
                ((float4*)(sAn + rl0 * FEAT))[lane]       = a0;
                ((float4*)(sAn + (rl0 + 1) * FEAT))[lane] = a1;
            }

            // ---- GEMM chunk: k = c*32 .. c*32+31 ----
            const int k0c = c * 32;
            #pragma unroll 2
            for (int kc = 0; kc < 32; kc += 4) {
                float4 a[4];
                #pragma unroll
                for (int i = 0; i < 4; i++)
                    a[i] = *(const float4*)(aBase + i * FEAT + k0c + kc);

                #pragma unroll
                for (int kk = 0; kk < 4; kk++) {
                    const ulonglong2 b0 =
                        *(const ulonglong2*)(bBase + (k0c + kc + kk) * EMB);
                    const ulonglong2 b1 =
                        *(const ulonglong2*)(bBase + (k0c + kc + kk) * EMB + 64);
                    #pragma unroll
                    for (int i = 0; i < 4; i++) {
                        const float as = (kk == 0) ? a[i].x : (kk == 1) ? a[i].y
                                       : (kk == 2) ? a[i].z : a[i].w;
                        const ull av = pack2(as);
                        fma2(acc[i][0], av, b0.x);
                        fma2(acc[i][1], av, b0.y);
                        fma2(acc[i][2], av, b1.x);
                        fma2(acc[i][3], av, b1.y);
                    }
                }
            }
        }

        // ---- epilogue: write pre-BN x + packed column stats ----
        #pragma unroll
        for (int i = 0; i < 4; i++) {
            const int rg = rowBase + ty * 4 + i;
            if (rg < NB_ROWS) {
                ulonglong2 v0; v0.x = acc[i][0]; v0.y = acc[i][1];
                ulonglong2 v1; v1.x = acc[i][2]; v1.y = acc[i][3];
                *(ulonglong2*)(out + (long long)rg * EMB + tx * 4)      = v0;
                *(ulonglong2*)(out + (long long)rg * EMB + 64 + tx * 4) = v1;
            }
            #pragma unroll
            for (int j = 0; j < 4; j++) {          // pad rows are exact 0
                add2(cs[j], acc[i][j]);
                fma2(cq[j], acc[i][j], acc[i][j]);
            }
        }

        t = tn;
        p ^= 1;
    }

    // ====================== CTA-level stats reduce ======================
    __syncthreads();           // no further A reads; reuse A[0] region
    float* s_sum = (float*)(smem + SM_A);           // [32][128]
    float* s_sq  = (float*)(smem + SM_A) + 4096;    // [32][128]
    #pragma unroll
    for (int j = 0; j < 4; j++) {
        float s0, s1, q0, q1;
        unpack2(cs[j], s0, s1);
        unpack2(cq[j], q0, q1);
        const int c = (j < 2) ? (tx * 4 + 2 * j) : (64 + tx * 4 + 2 * (j - 2));
        s_sum[ty * 128 + c]     = s0;
        s_sum[ty * 128 + c + 1] = s1;
        s_sq [ty * 128 + c]     = q0;
        s_sq [ty * 128 + c + 1] = q1;
    }
    __syncthreads();
    if (tid < 128) {
        float s = 0.f, q = 0.f;
        #pragma unroll
        for (int r = 0; r < 32; r++) {
            s += s_sum[r * 128 + tid];
            q += s_sq [r * 128 + tid];
        }
        g_psum[bid * 128 + tid] = s;
        g_psq [bid * 128 + tid] = q;
    }

    // ========================== grid barrier ==========================
    __threadfence();
    __shared__ unsigned int sh_last;
    if (tid == 0)
        sh_last = (atomicAdd(&g_arrival, 1u) == (unsigned)(GRID - 1)) ? 1u : 0u;
    __syncthreads();

    if (sh_last) {
        if (tid < 256) {
            const int c = tid & 127, pp = tid >> 7;    // 2-way split
            float s = 0.f, q = 0.f;
            for (int b = pp; b < GRID; b += 2) {
                s += g_psum[b * 128 + c];
                q += g_psq [b * 128 + c];
            }
            s_sum[pp * 128 + c] = s;
            s_sq [pp * 128 + c] = q;
        }
        __syncthreads();
        if (tid < 128) {
            const float sum = s_sum[tid] + s_sum[128 + tid];
            const float sqq = s_sq [tid] + s_sq [128 + tid];
            const float invN = 1.0f / (float)NB_ROWS;
            const float mean = sum * invN;
            const float var  = sqq * invN - mean * mean;
            const float sc   = gamma[tid] * rsqrtf(var + 1e-5f);
            g_scale[tid] = sc;
            g_bias [tid] = beta[tid] - mean * sc;
        }
        __syncthreads();
        __threadfence();
        if (tid == 0) atomicExch(&g_ready, 1u);
    } else {
        if (tid == 0) {
            unsigned int r;
            do {
                asm volatile("ld.acquire.gpu.b32 %0, [%1];"
                             : "=r"(r) : "l"(&g_ready));
                if (!r) __nanosleep(64);
            } while (!r);
        }
        __syncthreads();
    }

    // ---- BN apply + LeakyReLU (static tile assignment) ----
    __syncthreads();
    if (tid < 128) {
        s_w[tid]       = g_scale[tid];
        s_w[128 + tid] = g_bias[tid];
    }
    __syncthreads();

    for (int tt = bid; tt < NTILE; tt += GRID) {
        const int rowBase = tt * MTILE;
        float4* o4 = (float4*)(out + (long long)rowBase * EMB);
        #pragma unroll
        for (int j = 0; j < 8; j++) {
            const int i = tid + j * TPB;               // 0..4095 float4s
            const int row = i >> 5;
            if (rowBase + row < NB_ROWS) {
                const int c4 = i & 31;
                float4 v = o4[i];
                const float4 sc = ((const float4*)s_w)[c4];
                const float4 bs = ((const float4*)(s_w + 128))[c4];
                float x;
                x = v.x * sc.x + bs.x; v.x = (x >= 0.f) ? x : 0.01f * x;
                x = v.y * sc.y + bs.y; v.y = (x >= 0.f) ? x : 0.01f * x;
                x = v.z * sc.z + bs.z; v.z = (x >= 0.f) ? x : 0.01f * x;
                x = v.w * sc.w + bs.w; v.w = (x >= 0.f) ? x : 0.01f * x;
                o4[i] = v;
            }
        }
    }

    // ---- exit: last CTA resets counters for graph replay ----
    __threadfence();
    __syncthreads();
    if (tid == 0) {
        if (atomicAdd(&g_done, 1u) == (unsigned)(GRID - 1)) {
            g_tile    = 0;
            g_arrival = 0;
            g_done    = 0;
            g_ready   = 0;
            __threadfence();
        }
    }
}

// ============================================================================
extern "C" void kernel_launch(void* const* d_in, const int* in_sizes, int n_in,
                              void* d_out, int out_size)
{
    const float* raw   = (const float*)d_in[0];
    const float* W     = (const float*)d_in[1];
    const float* gamma = (const float*)d_in[2];
    const float* beta  = (const float*)d_in[3];
    const int*   nidx  = (const int*)d_in[4];
    float* out = (float*)d_out;

    cudaFuncSetAttribute(fused_pipe,
                         cudaFuncAttributeMaxDynamicSharedMemorySize,
                         SMEM_BYTES);

    fused_pipe<<<GRID, TPB, SMEM_BYTES>>>(raw, W, nidx, gamma, beta, out);
}